// round 1
// baseline (speedup 1.0000x reference)
#include <cuda_runtime.h>
#include <cuda_fp16.h>

#define BB   32
#define NIN  2048
#define DIN  16
#define JJ   64
#define CC   32
#define NITR 5

// 256 MB fp16 scratch for u_hat, layout [b][j][i][c]
__device__ __half g_uhat[(size_t)BB * JJ * NIN * CC];

// ---------- packed f32x2 helpers (sm_103a FFMA2 is PTX-only) ----------
__device__ __forceinline__ unsigned long long pack2(float x, float y) {
    unsigned long long r;
    asm("mov.b64 %0, {%1, %2};" : "=l"(r) : "f"(x), "f"(y));
    return r;
}
__device__ __forceinline__ void unpack2(unsigned long long v, float& x, float& y) {
    asm("mov.b64 {%0, %1}, %2;" : "=f"(x), "=f"(y) : "l"(v));
}
__device__ __forceinline__ unsigned long long ffma2(unsigned long long a,
                                                    unsigned long long b,
                                                    unsigned long long c) {
    unsigned long long d;
    asm("fma.rn.f32x2 %0, %1, %2, %3;" : "=l"(d) : "l"(a), "l"(b), "l"(c));
    return d;
}

// =====================================================================
// Phase 1: u_hat[b,i,j,c] = sum_d u[b,i,d] * W[i,j,c,d]   (fp32 -> fp16)
// One block per input capsule i. 256 threads; each thread owns 8 jc
// columns and all 32 batches (as 16 f32x2 batch-pairs).
// =====================================================================
__global__ __launch_bounds__(256) void uhat_kernel(const float* __restrict__ x,
                                                   const float* __restrict__ W) {
    const int i   = blockIdx.x;
    const int tid = threadIdx.x;

    // u slice for this i, packed as batch-pairs: u2s[bp*16 + d] = {u[2bp,d], u[2bp+1,d]}
    __shared__ unsigned long long u2s[16 * 16];
    for (int k = tid; k < 512; k += 256) {
        int b = k >> 4, d = k & 15;
        float val = x[((size_t)b * NIN + i) * DIN + d];
        reinterpret_cast<float*>(u2s)[((b >> 1) * 16 + d) * 2 + (b & 1)] = val;
    }
    __syncthreads();

    const float* wbase = W + (size_t)i * (JJ * CC * DIN);

    #pragma unroll 1
    for (int r = 0; r < 8; ++r) {
        const int jc = (r << 8) + tid;                 // warp stays inside one j
        const float4* wr = reinterpret_cast<const float4*>(wbase + jc * DIN);
        float4 w0 = wr[0], w1 = wr[1], w2 = wr[2], w3 = wr[3];
        float wreg[16] = {w0.x, w0.y, w0.z, w0.w, w1.x, w1.y, w1.z, w1.w,
                          w2.x, w2.y, w2.z, w2.w, w3.x, w3.y, w3.z, w3.w};

        unsigned long long acc[16];
        #pragma unroll
        for (int bp = 0; bp < 16; ++bp) acc[bp] = 0ULL;

        #pragma unroll
        for (int d = 0; d < 16; ++d) {
            unsigned long long wd2 = pack2(wreg[d], wreg[d]);
            #pragma unroll
            for (int bp = 0; bp < 16; ++bp)
                acc[bp] = ffma2(u2s[bp * 16 + d], wd2, acc[bp]);
        }

        const int j = jc >> 5, c = jc & 31;
        const unsigned base = (unsigned)j * (NIN * CC) + (unsigned)i * CC + (unsigned)c;
        #pragma unroll
        for (int bp = 0; bp < 16; ++bp) {
            float fx, fy;
            unpack2(acc[bp], fx, fy);
            g_uhat[base + (unsigned)(2 * bp)     * (JJ * NIN * CC)] = __float2half_rn(fx);
            g_uhat[base + (unsigned)(2 * bp + 1) * (JJ * NIN * CC)] = __float2half_rn(fy);
        }
    }
}

// =====================================================================
// Phase 2: dynamic routing. One block per (b,j). The 2048x32 fp16 u_hat
// slice lives in SMEM (chunk-swizzled against LDS bank conflicts); the
// routing logits b[i] live in SMEM; all 5 iterations run on-chip.
// Per iteration, a SINGLE pass over i fuses:
//   b[i] += <v_prev, uh_i>;  e = exp(b[i]);  Z += e;  s += e*uh_i
// (no softmax max-shift needed: |b| stays << 88, exp() is fp32-safe)
// =====================================================================
#define RT_THREADS 512
#define RT_WARPS   16
#define IPT        (NIN / RT_THREADS)   // 4 capsules per thread

#define RT_SMEM (NIN * CC * 2 /*uh fp16*/ + NIN * 4 /*b logits*/ \
                 + RT_WARPS * CC * 4 /*warp s partials*/ + RT_WARPS * 4 /*warp Z*/ + CC * 4 /*v*/)

__global__ __launch_bounds__(RT_THREADS, 1) void routing_kernel(float* __restrict__ out) {
    extern __shared__ unsigned char smem_raw[];
    uint4* uh4  = reinterpret_cast<uint4*>(smem_raw);                   // NIN rows x 4 chunks (16B)
    float* bl   = reinterpret_cast<float*>(smem_raw + NIN * CC * 2);    // NIN logits
    float* wsum = bl + NIN;                                             // [16][32]
    float* wz   = wsum + RT_WARPS * CC;                                 // [16]
    float* vv   = wz + RT_WARPS;                                        // [32]

    const int bj   = blockIdx.x;          // bj = b*J + j, matches uhat + output layouts
    const int tid  = threadIdx.x;
    const int wid  = tid >> 5;
    const int lane = tid & 31;

    // Bulk-load the 128KB slice; chunk k of row i goes to slot (i*4) | (k ^ ((i>>1)&3))
    // so that 8 consecutive rows hit 8 distinct LDS.128 bank groups.
    const uint4* src = reinterpret_cast<const uint4*>(g_uhat + (size_t)bj * NIN * CC);
    for (int m = tid; m < NIN * 4; m += RT_THREADS) {
        int i = m >> 2, k = m & 3;
        uh4[(i << 2) | (k ^ ((i >> 1) & 3))] = src[m];
    }
    for (int k = tid; k < NIN; k += RT_THREADS) bl[k] = 0.0f;
    __syncthreads();

    float vr[CC];                          // current v, broadcast in registers

    for (int it = 0; it < NITR; ++it) {
        float z_t = 0.0f;
        float sacc[CC];
        #pragma unroll
        for (int c = 0; c < CC; ++c) sacc[c] = 0.0f;

        #pragma unroll
        for (int ii = 0; ii < IPT; ++ii) {
            const int i  = ii * RT_THREADS + tid;
            const int sw = (i >> 1) & 3;
            uint4 q0 = uh4[(i << 2) | (0 ^ sw)];
            uint4 q1 = uh4[(i << 2) | (1 ^ sw)];
            uint4 q2 = uh4[(i << 2) | (2 ^ sw)];
            uint4 q3 = uh4[(i << 2) | (3 ^ sw)];

            float uf[CC];
            {
                const unsigned w[16] = {q0.x, q0.y, q0.z, q0.w, q1.x, q1.y, q1.z, q1.w,
                                        q2.x, q2.y, q2.z, q2.w, q3.x, q3.y, q3.z, q3.w};
                #pragma unroll
                for (int k = 0; k < 16; ++k) {
                    __half2 h = *reinterpret_cast<const __half2*>(&w[k]);
                    float2 f  = __half22float2(h);
                    uf[2 * k]     = f.x;
                    uf[2 * k + 1] = f.y;
                }
            }

            float e;
            if (it == 0) {
                e = 1.0f;                              // softmax(0) -> uniform
            } else {
                float dot = 0.0f;
                #pragma unroll
                for (int c = 0; c < CC; ++c) dot = fmaf(vr[c], uf[c], dot);
                float bn = bl[i] + dot;                // agreement update
                bl[i] = bn;
                e = __expf(bn);                        // unnormalized softmax weight
            }
            z_t += e;
            #pragma unroll
            for (int c = 0; c < CC; ++c) sacc[c] = fmaf(e, uf[c], sacc[c]);
        }

        // warp-level reduce of Z and the 32-vector s
        #pragma unroll
        for (int off = 16; off; off >>= 1) z_t += __shfl_xor_sync(0xffffffffu, z_t, off);
        #pragma unroll
        for (int c = 0; c < CC; ++c) {
            #pragma unroll
            for (int off = 16; off; off >>= 1)
                sacc[c] += __shfl_xor_sync(0xffffffffu, sacc[c], off);
        }
        if (lane == 0) {
            wz[wid] = z_t;
            #pragma unroll
            for (int c = 0; c < CC; ++c) wsum[wid * CC + c] = sacc[c];
        }
        __syncthreads();

        // cross-warp combine + squash (warp 0, lane c owns component c)
        if (wid == 0) {
            float s = 0.0f;
            #pragma unroll
            for (int w = 0; w < RT_WARPS; ++w) s += wsum[w * CC + lane];
            float zz = (lane < RT_WARPS) ? wz[lane] : 0.0f;
            #pragma unroll
            for (int off = 16; off; off >>= 1) zz += __shfl_xor_sync(0xffffffffu, zz, off);
            s /= zz;
            float vc = s + 1e-7f;                      // Keras eps
            float nn = vc * vc;
            #pragma unroll
            for (int off = 16; off; off >>= 1) nn += __shfl_xor_sync(0xffffffffu, nn, off);
            float sc = nn / ((1.0f + nn) * sqrtf(nn)); // n/(1+n)/sqrt(n)
            vv[lane] = vc * sc;
        }
        __syncthreads();
        #pragma unroll
        for (int c = 0; c < CC; ++c) vr[c] = vv[c];
    }

    if (tid < CC) out[(size_t)bj * CC + tid] = vv[tid];
}

// =====================================================================
extern "C" void kernel_launch(void* const* d_in, const int* in_sizes, int n_in,
                              void* d_out, int out_size) {
    const float* x = (const float*)d_in[0];
    const float* W = (const float*)d_in[1];
    if (n_in >= 2 && in_sizes[0] > in_sizes[1]) {  // x is the smaller input
        const float* t = x; x = W; W = t;
    }

    cudaFuncSetAttribute(routing_kernel,
                         cudaFuncAttributeMaxDynamicSharedMemorySize, RT_SMEM);

    uhat_kernel<<<NIN, 256>>>(x, W);
    routing_kernel<<<BB * JJ, RT_THREADS, RT_SMEM>>>((float*)d_out);
    (void)out_size;
}

// round 2
// speedup vs baseline: 1.7180x; 1.7180x over previous
#include <cuda_runtime.h>
#include <cuda_fp16.h>

#define BB   32
#define NIN  2048
#define DIN  16
#define JJ   64
#define CC   32
#define NITR 5

#define PLANE 4194304u   // JJ*NIN*CC, elements per batch-plane of g_uhat

// 256 MB fp16 scratch for u_hat, layout [b][j][i][c]
__device__ __half g_uhat[(size_t)BB * JJ * NIN * CC];

// ---------- packed f32x2 helpers (FFMA2 is PTX-only on sm_103a) ----------
__device__ __forceinline__ unsigned long long pack2(float x, float y) {
    unsigned long long r;
    asm("mov.b64 %0, {%1, %2};" : "=l"(r) : "f"(x), "f"(y));
    return r;
}
__device__ __forceinline__ void unpack2(unsigned long long v, float& x, float& y) {
    asm("mov.b64 {%0, %1}, %2;" : "=f"(x), "=f"(y) : "l"(v));
}
__device__ __forceinline__ unsigned long long ffma2(unsigned long long a,
                                                    unsigned long long b,
                                                    unsigned long long c) {
    unsigned long long d;
    asm("fma.rn.f32x2 %0, %1, %2, %3;" : "=l"(d) : "l"(a), "l"(b), "l"(c));
    return d;
}

// =====================================================================
// Phase 1: u_hat[b,i,j,c] = sum_d u[b,i,d] * W[i,j,c,d]   (fp32 -> fp16)
// One block per input capsule i; 256 threads; thread owns 8 jc columns.
// Register-bounded: accumulate 8 batch-pairs (16 regs) at a time.
// =====================================================================
__global__ __launch_bounds__(256) void uhat_kernel(const float* __restrict__ x,
                                                   const float* __restrict__ W) {
    const int i   = blockIdx.x;
    const int tid = threadIdx.x;

    __shared__ float u_s[16 * 32];   // [d][b]
    for (int k = tid; k < 512; k += 256) {
        int b = k >> 4, d = k & 15;
        u_s[d * 32 + b] = x[((size_t)b * NIN + i) * DIN + d];
    }
    __syncthreads();

    const float* wbase = W + (size_t)i * (JJ * CC * DIN);

    #pragma unroll 1
    for (int r = 0; r < 8; ++r) {
        const int jc = (r << 8) + tid;
        const float4* wr = reinterpret_cast<const float4*>(wbase + jc * DIN);
        float4 w0 = wr[0], w1 = wr[1], w2 = wr[2], w3 = wr[3];
        unsigned long long wd2[16];
        wd2[0]  = pack2(w0.x, w0.x); wd2[1]  = pack2(w0.y, w0.y);
        wd2[2]  = pack2(w0.z, w0.z); wd2[3]  = pack2(w0.w, w0.w);
        wd2[4]  = pack2(w1.x, w1.x); wd2[5]  = pack2(w1.y, w1.y);
        wd2[6]  = pack2(w1.z, w1.z); wd2[7]  = pack2(w1.w, w1.w);
        wd2[8]  = pack2(w2.x, w2.x); wd2[9]  = pack2(w2.y, w2.y);
        wd2[10] = pack2(w2.z, w2.z); wd2[11] = pack2(w2.w, w2.w);
        wd2[12] = pack2(w3.x, w3.x); wd2[13] = pack2(w3.y, w3.y);
        wd2[14] = pack2(w3.z, w3.z); wd2[15] = pack2(w3.w, w3.w);

        const int j = jc >> 5, c = jc & 31;
        const unsigned base = (unsigned)j * (NIN * CC) + (unsigned)i * CC + (unsigned)c;

        #pragma unroll 1
        for (int h = 0; h < 2; ++h) {            // batch halves: b in [16h, 16h+16)
            unsigned long long acc[8];
            #pragma unroll
            for (int k = 0; k < 8; ++k) acc[k] = 0ULL;

            #pragma unroll 4
            for (int d = 0; d < 16; ++d) {
                const float4* up = reinterpret_cast<const float4*>(u_s + d * 32 + h * 16);
                float4 q0 = up[0], q1 = up[1], q2 = up[2], q3 = up[3];
                acc[0] = ffma2(pack2(q0.x, q0.y), wd2[d], acc[0]);
                acc[1] = ffma2(pack2(q0.z, q0.w), wd2[d], acc[1]);
                acc[2] = ffma2(pack2(q1.x, q1.y), wd2[d], acc[2]);
                acc[3] = ffma2(pack2(q1.z, q1.w), wd2[d], acc[3]);
                acc[4] = ffma2(pack2(q2.x, q2.y), wd2[d], acc[4]);
                acc[5] = ffma2(pack2(q2.z, q2.w), wd2[d], acc[5]);
                acc[6] = ffma2(pack2(q3.x, q3.y), wd2[d], acc[6]);
                acc[7] = ffma2(pack2(q3.z, q3.w), wd2[d], acc[7]);
            }

            #pragma unroll
            for (int k = 0; k < 8; ++k) {
                float fx, fy;
                unpack2(acc[k], fx, fy);
                const unsigned b0 = (unsigned)(h * 16 + 2 * k);
                g_uhat[base + b0 * PLANE]       = __float2half_rn(fx);
                g_uhat[base + (b0 + 1) * PLANE] = __float2half_rn(fy);
            }
        }
    }
}

// =====================================================================
// Phase 2: dynamic routing, 2-CTA cluster per (b,j).
// Each CTA holds 1024 rows of u_hat as fp32 in SMEM (no per-iteration
// cvt), logits in SMEM, and exchanges its partial (Z, s[32]) with the
// peer CTA via DSMEM + barrier.cluster each iteration. Both CTAs
// compute v identically (2-term add is commutative -> bit-identical).
// =====================================================================
#define RT_THREADS 512
#define IH 1024                      // rows per CTA

// smem floats: uh 32768 | bl 1024 | wsum 512 | wz 16 | rs 32 | rz 4 | vv 32
#define SM_UH   0
#define SM_BL   (IH * CC)
#define SM_WSUM (SM_BL + IH)
#define SM_WZ   (SM_WSUM + 16 * 32)
#define SM_RS   (SM_WZ + 16)
#define SM_RZ   (SM_RS + 32)
#define SM_VV   (SM_RZ + 4)
#define RT_SMEM ((SM_VV + 32) * 4)

__device__ __forceinline__ void st_peer_f32(float* p, unsigned peer, float v) {
    unsigned a = (unsigned)__cvta_generic_to_shared(p);
    unsigned r;
    asm("mapa.shared::cluster.u32 %0, %1, %2;" : "=r"(r) : "r"(a), "r"(peer));
    asm volatile("st.shared::cluster.f32 [%0], %1;" :: "r"(r), "f"(v) : "memory");
}
__device__ __forceinline__ void cluster_sync_() {
    asm volatile("barrier.cluster.arrive.aligned;" ::: "memory");
    asm volatile("barrier.cluster.wait.aligned;" ::: "memory");
}

__global__ __launch_bounds__(RT_THREADS, 1) __cluster_dims__(2, 1, 1)
void routing_kernel(float* __restrict__ out) {
    extern __shared__ unsigned char sm_raw[];
    float* smf  = reinterpret_cast<float*>(sm_raw);
    float* uh   = smf + SM_UH;
    float* bl   = smf + SM_BL;
    float* wsum = smf + SM_WSUM;
    float* wz   = smf + SM_WZ;
    float* rs   = smf + SM_RS;
    float* rz   = smf + SM_RZ;
    float* vv   = smf + SM_VV;

    const int tid  = threadIdx.x;
    const int wid  = tid >> 5;
    const int lane = tid & 31;
    unsigned rank;
    asm("mov.u32 %0, %%cluster_ctarank;" : "=r"(rank));
    const unsigned peer = rank ^ 1u;
    const int bj = blockIdx.x >> 1;

    // ---- load 1024 rows fp16 -> fp32 SMEM (chunk-swizzled: phys = k ^ (row&7))
    const uint4* src = reinterpret_cast<const uint4*>(
        g_uhat + ((size_t)bj * NIN + (size_t)rank * IH) * CC);
    #pragma unroll
    for (int t = 0; t < 8; ++t) {
        int m = t * RT_THREADS + tid;          // 4096 fp16 16B-chunks
        int row = m >> 2, k = m & 3, sw = row & 7;
        uint4 q = src[m];
        float2 f0 = __half22float2(*reinterpret_cast<__half2*>(&q.x));
        float2 f1 = __half22float2(*reinterpret_cast<__half2*>(&q.y));
        float2 f2 = __half22float2(*reinterpret_cast<__half2*>(&q.z));
        float2 f3 = __half22float2(*reinterpret_cast<__half2*>(&q.w));
        float4* dst = reinterpret_cast<float4*>(uh + row * 32);
        dst[(2 * k)     ^ sw] = make_float4(f0.x, f0.y, f1.x, f1.y);
        dst[(2 * k + 1) ^ sw] = make_float4(f2.x, f2.y, f3.x, f3.y);
    }
    for (int t = tid; t < IH; t += RT_THREADS) bl[t] = 0.0f;
    __syncthreads();

    unsigned long long vr2[16];   // packed v (c-pairs)

    for (int it = 0; it < NITR; ++it) {
        unsigned long long s2[16];
        #pragma unroll
        for (int m = 0; m < 16; ++m) s2[m] = 0ULL;
        float z = 0.0f;

        #pragma unroll
        for (int t = 0; t < 2; ++t) {
            const int i  = t * RT_THREADS + tid;
            const int sw = i & 7;
            const float4* rowp = reinterpret_cast<const float4*>(uh + i * 32);

            float e;
            if (it == 0) {
                e = 1.0f;                         // softmax(0) -> uniform
            } else {
                unsigned long long d2 = 0ULL;     // pass A: agreement dot
                #pragma unroll
                for (int kk = 0; kk < 8; ++kk) {
                    float4 q = rowp[kk ^ sw];
                    d2 = ffma2(pack2(q.x, q.y), vr2[2 * kk],     d2);
                    d2 = ffma2(pack2(q.z, q.w), vr2[2 * kk + 1], d2);
                }
                float dx, dy;
                unpack2(d2, dx, dy);
                float bn = bl[i] + dx + dy;
                bl[i] = bn;
                e = __expf(bn);                   // no max-shift needed: |b| stays small
            }
            z += e;
            const unsigned long long e2 = pack2(e, e);
            #pragma unroll
            for (int kk = 0; kk < 8; ++kk) {      // pass B: s += e * u_hat_i
                float4 q = rowp[kk ^ sw];
                s2[2 * kk]     = ffma2(pack2(q.x, q.y), e2, s2[2 * kk]);
                s2[2 * kk + 1] = ffma2(pack2(q.z, q.w), e2, s2[2 * kk + 1]);
            }
        }

        // ---- butterfly-SPLIT warp reduction: lane ends with sum for c=lane
        float v[32];
        #pragma unroll
        for (int m = 0; m < 16; ++m) unpack2(s2[m], v[2 * m], v[2 * m + 1]);
        #pragma unroll
        for (int mm = 16; mm >= 1; mm >>= 1) {
            const bool hi = (lane & mm) != 0;
            #pragma unroll
            for (int k = 0; k < mm; ++k) {
                float send = hi ? v[k] : v[k + mm];
                float recv = __shfl_xor_sync(0xffffffffu, send, mm);
                v[k] = (hi ? v[k + mm] : v[k]) + recv;
            }
        }
        #pragma unroll
        for (int o = 16; o; o >>= 1) z += __shfl_xor_sync(0xffffffffu, z, o);

        wsum[wid * 32 + lane] = v[0];
        if (lane == 0) wz[wid] = z;
        __syncthreads();

        // ---- cross-warp combine + DSMEM exchange (warp 0)
        float s_loc = 0.0f, z_loc = 0.0f;
        if (wid == 0) {
            #pragma unroll
            for (int w = 0; w < 16; ++w) s_loc += wsum[w * 32 + lane];
            float zz = (lane < 16) ? wz[lane] : 0.0f;
            #pragma unroll
            for (int o = 16; o; o >>= 1) zz += __shfl_xor_sync(0xffffffffu, zz, o);
            z_loc = zz;
            st_peer_f32(rs + lane, peer, s_loc);
            if (lane == 0) st_peer_f32(rz, peer, z_loc);
        }
        cluster_sync_();

        if (wid == 0) {
            float s_tot = s_loc + rs[lane];
            float z_tot = z_loc + rz[0];
            float s  = s_tot / z_tot;
            float vc = s + 1e-7f;                 // Keras eps
            float nn = vc * vc;
            #pragma unroll
            for (int o = 16; o; o >>= 1) nn += __shfl_xor_sync(0xffffffffu, nn, o);
            float sc = nn / ((1.0f + nn) * sqrtf(nn));   // n/(1+n)/sqrt(n)
            vv[lane] = vc * sc;
        }
        __syncthreads();

        if (it < NITR - 1) {
            const float4* vp = reinterpret_cast<const float4*>(vv);
            #pragma unroll
            for (int kk = 0; kk < 8; ++kk) {
                float4 q = vp[kk];
                vr2[2 * kk]     = pack2(q.x, q.y);
                vr2[2 * kk + 1] = pack2(q.z, q.w);
            }
        }
    }

    if (rank == 0 && wid == 0) out[(size_t)bj * CC + lane] = vv[lane];
}

// =====================================================================
extern "C" void kernel_launch(void* const* d_in, const int* in_sizes, int n_in,
                              void* d_out, int out_size) {
    const float* x = (const float*)d_in[0];
    const float* W = (const float*)d_in[1];
    if (n_in >= 2 && in_sizes[0] > in_sizes[1]) {  // x is the smaller input
        const float* t = x; x = W; W = t;
    }

    cudaFuncSetAttribute(routing_kernel,
                         cudaFuncAttributeMaxDynamicSharedMemorySize, RT_SMEM);

    uhat_kernel<<<NIN, 256>>>(x, W);
    routing_kernel<<<BB * JJ * 2, RT_THREADS, RT_SMEM>>>((float*)d_out);
    (void)out_size;
}